// round 6
// baseline (speedup 1.0000x reference)
#include <cuda_runtime.h>
#include <math.h>

#define NT 128
#define GZ (-9.80665f)

struct SM {
    float A[441], Pn[441], T9[189], L[108];
    float H[24], G[36], GA[42], HP[42], S3[3], r2[2];
    float Rotn[9], Vn[3], Pn3[3], Om[3], vi[3];
    float mir[33];     // Rot 0-8, V 9-11, Pp 12-14, Bom 15-17, Bac 18-20, Rci 21-29, Tci 30-32
    float in[2][9];    // t, u[6], mcov[2]
};

__device__ __forceinline__ float skf(const float* w, int r, int c) {
    if (r == 0) return (c == 0) ? 0.f : ((c == 1) ? -w[2] : w[1]);
    if (r == 1) return (c == 0) ? w[2] : ((c == 1) ? 0.f : -w[0]);
    return (c == 0) ? -w[1] : ((c == 1) ? w[0] : 0.f);
}
__device__ __forceinline__ float skewrowdot(const float* w, const float* R, int rr, int j) {
    if (rr == 0) return -w[2]*R[3+j] + w[1]*R[6+j];
    if (rr == 1) return  w[2]*R[0+j] - w[0]*R[6+j];
    return -w[1]*R[0+j] + w[0]*R[3+j];
}
__device__ __forceinline__ float SG(int rr, int j) {
    if (rr == 0 && j == 1) return -GZ;
    if (rr == 1 && j == 0) return  GZ;
    return 0.f;
}
__device__ __forceinline__ float sgR(const float* R, int rr, int j) {
    if (rr == 0) return -GZ * R[3+j];
    if (rr == 1) return  GZ * R[0+j];
    return 0.f;
}
__device__ __forceinline__ void so3c(float a2, float& c, float& sa, float& oc) {
    c  = 1.f + a2*(-0.5f      + a2*((1.f/24.f)  + a2*(-1.f/720.f)));
    sa = 1.f + a2*((-1.f/6.f) + a2*((1.f/120.f) + a2*(-1.f/5040.f)));
    oc = 0.5f + a2*((-1.f/24.f) + a2*(1.f/720.f));
}
__device__ __forceinline__ float j1c(float a2) {
    return (1.f/6.f) + a2*((-1.f/120.f) + a2*(1.f/5040.f));
}
__device__ __forceinline__ void mm3(const float* A, const float* B, float* C) {
#pragma unroll
    for (int p = 0; p < 3; ++p)
#pragma unroll
        for (int q = 0; q < 3; ++q)
            C[p*3+q] = A[p*3+0]*B[0*3+q] + A[p*3+1]*B[1*3+q] + A[p*3+2]*B[2*3+q];
}
__device__ __forceinline__ void normrot(float* X) {
    for (int it = 0; it < 8; ++it) {
        float Y[9], Z[9];
#pragma unroll
        for (int p = 0; p < 3; ++p)
#pragma unroll
            for (int q = 0; q < 3; ++q)
                Y[p*3+q] = X[p*3+0]*X[q*3+0] + X[p*3+1]*X[q*3+1] + X[p*3+2]*X[q*3+2];
        mm3(Y, X, Z);
#pragma unroll
        for (int m = 0; m < 9; ++m) X[m] = 1.5f*X[m] - 0.5f*Z[m];
    }
}

#define BAR_SYNC_128(id)   asm volatile("bar.sync " #id ", 128;" ::: "memory")
#define BAR_SYNC_96(id)    asm volatile("bar.sync " #id ", 96;"  ::: "memory")
#define BAR_ARRIVE_128(id) asm volatile("bar.arrive " #id ", 128;" ::: "memory")

__global__ void __launch_bounds__(NT, 1)
iekf_kernel(const float* __restrict__ t, const float* __restrict__ u,
            const float* __restrict__ mc, const float* __restrict__ vmes,
            const float* __restrict__ ang0, float* __restrict__ out, int N)
{
    __shared__ SM s;
    const int tid = threadIdx.x;
    const bool isMat = (tid < 96);
    const int ln = tid - 96;

    // ---------- W0-2 decodes: 5 slots/thread ----------
    bool eV[5]; int eII[5], eJJ[5], eJJT[5], eIIB[5], eJJ12[5];
    int eAm[5], eAr[5], eBrx[5]; float eAsc[5], eAqv[5]; bool eT9f[5];
    float Preg[5];
#pragma unroll
    for (int sl = 0; sl < 5; ++sl) {
        int e = tid + sl*96;
        eV[sl] = isMat && (e < 441);
        int ii = 0, jj = 0;
        if (eV[sl]) { ii = e/21; jj = e - ii*21; }
        eII[sl]=ii; eJJ[sl]=jj; eJJT[sl]=jj*21+ii; eIIB[sl]=ii*21; eJJ12[sl]=jj*12;
        eT9f[sl] = (ii < 9);
        int am = 2, ar = 0, brx = 0; float asc = 0.f, aqv = 0.f;
        if (ii<3 && jj<3)                      { am=0; ar=ii*3;     brx=jj*3;     asc=0.001f; }
        else if (ii>=3&&ii<6&&jj>=3&&jj<6)     { am=0; ar=(ii-3)*3; brx=(jj-3)*3; asc=0.01f;  }
        else if (ii==jj) { am=1; aqv=(ii>=9&&ii<12)?6e-9f:(ii>=12&&ii<15)?2e-4f:(ii>=15)?1e-9f:0.f; }
        eAm[sl]=am; eAr[sl]=ar; eBrx[sl]=brx; eAsc[sl]=asc; eAqv[sl]=aqv;
        // P init
        float pv = 0.f;
        if (ii == jj) {
            if (ii < 2) pv = 0.001f;
            else if (ii >= 3 && ii < 5) pv = 0.1f;
            else if (ii >= 9 && ii < 12) pv = 0.006f;
            else if (ii >= 12 && ii < 15) pv = 0.004f;
            else if (ii >= 15 && ii < 18) pv = 1e-6f;
            else if (ii >= 18) pv = 0.005f;
        }
        Preg[sl] = pv;
    }
    // T9 slots (W0-2)
    const int t9aR12 = (tid/21)*12, t9aC = tid - (tid/21)*21;
    const int t9k2 = tid + 96; const bool t9bV = isMat && (t9k2 < 189);
    int t9bR12 = 0, t9bC = 0;
    if (t9bV) { int r = t9k2/21; t9bR12 = r*12; t9bC = t9k2 - r*21; }
    // L decodes (W0-2): slot1 k=tid, slot2 k=96+tid (tid<12 => row 8)
    int Lbrr = 0, Lrr = 0, Lbc = 0, Lj = 0;
    if (isMat) {
        int r = tid/12, cc = tid - r*12;
        Lbrr = r/3; Lrr = r - Lbrr*3; Lbc = cc/3; Lj = cc - Lbc*3;
    }
    const bool l2V = isMat && (tid < 12);
    const int L2bc = tid/3, L2j = tid - L2bc*3;    // row 8 -> brr=2, rr=2
    // W3 lane decodes
    const int rp = (ln >= 0 && ln < 9) ? ln/3 : 0;
    const int rq = (ln >= 0 && ln < 9) ? ln - rp*3 : 0;
    int ha = 0, hcc = 0, hbb = 0, hj = 0;
    if (ln >= 0 && ln < 24) { ha = ln/12; hcc = ln - ha*12; hbb = hcc/3; hj = hcc - hbb*3; }
    const int ga1A = (ln >= 21) ? 1 : 0;
    const int ga1C = (ln >= 0) ? (ln - ga1A*21) : 0;
    const int svW = (ln >= 9 && ln < 15) ? (ln-9)/3 : 0;
    const int svQ = (ln >= 9 && ln < 15) ? (ln-9) - svW*3 : 0;
    const int rcP = (ln >= 15 && ln < 24) ? (ln-15)/3 : 0;
    const int rcQ = (ln >= 15 && ln < 24) ? (ln-15) - rcP*3 : 0;
    // out pointers (W3)
    float* outP = out; int outStride = 0; float* outP2 = out;
    if (!isMat) {
        int idx = ln;
        if (idx < 9)       { outP = out + idx;             outStride = 9; }
        else if (idx < 12) { outP = out + 9*N  + (idx-9);  outStride = 3; }
        else if (idx < 15) { outP = out + 12*N + (idx-12); outStride = 3; }
        else if (idx < 18) { outP = out + 15*N + (idx-15); outStride = 3; }
        else if (idx < 21) { outP = out + 18*N + (idx-18); outStride = 3; }
        else if (idx < 30) { outP = out + 21*N + (idx-21); outStride = 9; }
        else               { outP = out + 30*N + (idx-30); outStride = 3; }
        outP2 = out + 30*N + 2;   // mir[32], lane 0 only
    }
    // prefetch pointers (W3 lanes 0..8)
    const float* pfP = t; int pfStride = 0;
    if (!isMat && ln < 9) {
        if (ln == 0)     { pfP = t  + 2;          pfStride = 1; }
        else if (ln < 7) { pfP = u  + 12 + (ln-1); pfStride = 6; }
        else             { pfP = mc + 4  + (ln-7); pfStride = 2; }
    }

    // ---------- prologue ----------
    float tprev = t[0];
    if (tid < 9) {
        float v;
        if (tid == 0) v = t[1];
        else if (tid < 7) v = u[6 + (tid-1)];
        else v = mc[2 + (tid-7)];
        s.in[1][tid] = v;
    }
    if (tid == 96) {
        float a0 = ang0[0], a1 = ang0[1], a2 = ang0[2];
        float cr = cosf(a0), sr = sinf(a0), cp = cosf(a1), sp = sinf(a1);
        float cy = cosf(a2), sy = sinf(a2);
        float Rx[9] = {1,0,0, 0,cr,-sr, 0,sr,cr};
        float Ry[9] = {cp,0,sp, 0,1,0, -sp,0,cp};
        float Rz[9] = {cy,-sy,0, sy,cy,0, 0,0,1};
        float T[9], R0[9];
        mm3(Rz, Ry, T); mm3(T, Rx, R0);
#pragma unroll
        for (int m = 0; m < 9; ++m) { s.mir[m] = R0[m]; s.mir[21+m] = (m==0||m==4||m==8) ? 1.f : 0.f; }
#pragma unroll
        for (int q = 0; q < 3; ++q) {
            s.mir[9+q] = vmes[q]; s.mir[12+q] = 0.f; s.mir[15+q] = 0.f;
            s.mir[18+q] = 0.f; s.mir[30+q] = 0.f;
        }
    }
    __syncthreads();
    if (!isMat) { __threadfence_block(); BAR_ARRIVE_128(5); }

    // ---------- main loop ----------
    for (int i = 1; i < N; ++i) {
        const int cur = i & 1;
        if (isMat) {
            BAR_SYNC_128(5);
            const float tcv = s.in[cur][0];
            const float dt = tcv - tprev; tprev = tcv;
            const float dt2 = dt*dt, dt3 = dt2*dt;
            // ---- s1: A from Preg, L ----
#pragma unroll
            for (int sl = 0; sl < 5; ++sl) if (eV[sl]) {
                int e = tid + sl*96;
                float gq = 0.f;
                if (eAm[sl] == 0) {
                    float d = s.mir[eAr[sl]]*s.mir[eBrx[sl]] + s.mir[eAr[sl]+1]*s.mir[eBrx[sl]+1]
                            + s.mir[eAr[sl]+2]*s.mir[eBrx[sl]+2];
                    gq = eAsc[sl] * dt2 * d;
                } else if (eAm[sl] == 1) gq = eAqv[sl] * dt2;
                s.A[e] = Preg[sl] + gq;
            }
            {
                const float* Rm = s.mir; const float* Vm = s.mir + 9; const float* Pm = s.mir + 12;
                float v = 0.f;
                if (Lbrr == 0) {
                    if (Lbc == 2) v = -dt * Rm[Lrr*3+Lj];
                } else if (Lbrr == 1) {
                    if (Lbc == 0)      v = dt * SG(Lrr, Lj);
                    else if (Lbc == 2) v = -dt*skewrowdot(Vm, Rm, Lrr, Lj) - 0.5f*dt2*sgR(Rm, Lrr, Lj);
                    else if (Lbc == 3) v = -dt * Rm[Lrr*3+Lj];
                } else {
                    if (Lbc == 0)      v = 0.5f*dt2*SG(Lrr, Lj);
                    else if (Lbc == 1) v = (Lrr == Lj) ? dt : 0.f;
                    else if (Lbc == 2) v = -dt*skewrowdot(Pm, Rm, Lrr, Lj)
                                           - 0.5f*dt2*skewrowdot(Vm, Rm, Lrr, Lj)
                                           - (dt3*(1.f/6.f))*sgR(Rm, Lrr, Lj);
                    else               v = -0.5f*dt2*Rm[Lrr*3+Lj];
                }
                s.L[tid] = v;
                if (l2V) {   // row 8 entries 96..107
                    float v2 = 0.f;
                    if (L2bc == 0)      v2 = 0.5f*dt2*SG(2, L2j);
                    else if (L2bc == 1) v2 = (2 == L2j) ? dt : 0.f;
                    else if (L2bc == 2) v2 = -dt*skewrowdot(Pm, Rm, 2, L2j)
                                             - 0.5f*dt2*skewrowdot(Vm, Rm, 2, L2j)
                                             - (dt3*(1.f/6.f))*sgR(Rm, 2, L2j);
                    else                v2 = -0.5f*dt2*Rm[6+L2j];
                    s.L[96+tid] = v2;
                }
            }
            __threadfence_block();
            BAR_ARRIVE_128(1);
            BAR_SYNC_96(2);
            // ---- s2: T9 ----
            {
                float a = s.A[tid];
#pragma unroll
                for (int m = 0; m < 12; ++m) {
                    int col = (m < 6) ? m : m + 3;
                    a += s.L[t9aR12+m] * s.A[col*21 + t9aC];
                }
                s.T9[tid] = a;
                if (t9bV) {
                    float b = s.A[t9k2];
#pragma unroll
                    for (int m = 0; m < 12; ++m) {
                        int col = (m < 6) ? m : m + 3;
                        b += s.L[t9bR12+m] * s.A[col*21 + t9bC];
                    }
                    s.T9[t9k2] = b;
                }
            }
            BAR_SYNC_96(3);
            // ---- s3: Pn ----
#pragma unroll
            for (int sl = 0; sl < 5; ++sl) if (eV[sl]) {
                int e = tid + sl*96;
                float b = eT9f[sl] ? s.T9[e] : s.A[e];
                if (eJJ[sl] < 9) {
#pragma unroll
                    for (int m = 0; m < 12; ++m) {
                        int col = (m < 6) ? m : m + 3;
                        float brc = eT9f[sl] ? s.T9[eIIB[sl]+col] : s.A[eIIB[sl]+col];
                        b += brc * s.L[eJJ12[sl]+m];
                    }
                }
                s.Pn[e] = b;
            }
            BAR_SYNC_128(4);
            // ---- s4: Joseph -> Preg ----
            {
                const float S00 = s.S3[0], S01 = s.S3[1], S11 = s.S3[2];
                const float idet = 1.f / (S00*S11 - S01*S01);
                const float Si00 = S11*idet, Si01 = -S01*idet, Si11 = S00*idet;
#pragma unroll
                for (int sl = 0; sl < 5; ++sl) if (eV[sl]) {
                    int e = tid + sl*96;
                    float hp0i = s.HP[eII[sl]], hp1i = s.HP[21+eII[sl]];
                    float hp0j = s.HP[eJJ[sl]], hp1j = s.HP[21+eJJ[sl]];
                    float Ki0 = Si00*hp0i + Si01*hp1i, Ki1 = Si01*hp0i + Si11*hp1i;
                    float Kj0 = Si00*hp0j + Si01*hp1j, Kj1 = Si01*hp0j + Si11*hp1j;
                    float KSi0 = Ki0*S00 + Ki1*S01, KSi1 = Ki0*S01 + Ki1*S11;
                    Preg[sl] = 0.5f*(s.Pn[e] + s.Pn[eJJT[sl]])
                             - (Ki0*hp0j + Ki1*hp1j) - (Kj0*hp0i + Kj1*hp1i)
                             + (KSi0*Kj0 + KSi1*Kj1);
                }
            }
        } else {
            // ================= warp 3 =================
            const float tcv = s.in[cur][0];
            const float dt = tcv - tprev; tprev = tcv;
            const float dt2 = dt*dt;
            // ---- c1: out, prefetch, chain ----
            *outP = s.mir[ln]; outP += outStride;
            if (ln == 0) { *outP2 = s.mir[32]; outP2 += 3; }
            float pf = 0.f;
            if (ln < 9 && (i + 1 < N)) { pf = *pfP; pfP += pfStride; }
            const float gy0 = s.in[cur][1], gy1 = s.in[cur][2], gy2 = s.in[cur][3];
            const float ac0 = s.in[cur][4], ac1 = s.in[cur][5], ac2 = s.in[cur][6];
            if (ln < 9) {
                float ph[3] = {(gy0 - s.mir[15])*dt, (gy1 - s.mir[16])*dt, (gy2 - s.mir[17])*dt};
                float a2 = ph[0]*ph[0] + ph[1]*ph[1] + ph[2]*ph[2];
                float c, sa, oc; so3c(a2, c, sa, oc);
                float e0 = ((0==rq)?c:0.f) + oc*ph[0]*ph[rq] + sa*skf(ph, 0, rq);
                float e1 = ((1==rq)?c:0.f) + oc*ph[1]*ph[rq] + sa*skf(ph, 1, rq);
                float e2 = ((2==rq)?c:0.f) + oc*ph[2]*ph[rq] + sa*skf(ph, 2, rq);
                s.Rotn[ln] = s.mir[rp*3+0]*e0 + s.mir[rp*3+1]*e1 + s.mir[rp*3+2]*e2;
            } else if (ln < 15) {
                float d0 = ac0 - s.mir[18], d1 = ac1 - s.mir[19], d2 = ac2 - s.mir[20];
                float accq = s.mir[svQ*3+0]*d0 + s.mir[svQ*3+1]*d1 + s.mir[svQ*3+2]*d2 + ((svQ==2)?GZ:0.f);
                if (svW == 0) s.Vn[svQ]  = s.mir[9+svQ] + accq*dt;
                else          s.Pn3[svQ] = s.mir[12+svQ] + s.mir[9+svQ]*dt + 0.5f*accq*dt2;
            } else if (ln < 18) {
                int q = ln - 15;
                s.Om[q] = ((q==0)?gy0:(q==1)?gy1:gy2) - s.mir[15+q];
            }
            __syncwarp();
            if (ln >= 18 && ln < 21) {
                int q = ln - 18;
                s.vi[q] = s.Rotn[q]*s.Vn[0] + s.Rotn[3+q]*s.Vn[1] + s.Rotn[6+q]*s.Vn[2];
            }
            __syncwarp();
            if (ln < 24) {
                float hv;
                if (hbb == 0) {
                    hv = s.Rotn[hj*3+0]*s.mir[21+ha+1] + s.Rotn[hj*3+1]*s.mir[24+ha+1] + s.Rotn[hj*3+2]*s.mir[27+ha+1];
                } else if (hbb == 1) {
                    hv = skf(s.mir+30, ha+1, hj);
                } else if (hbb == 2) {
                    hv = s.mir[21+ha+1]*skf(s.vi,0,hj) + s.mir[24+ha+1]*skf(s.vi,1,hj) + s.mir[27+ha+1]*skf(s.vi,2,hj);
                } else {
                    hv = -skf(s.Om, ha+1, hj);
                }
                s.H[ha*12+hcc] = hv;
            } else if (ln < 26) {
                int a = ln - 24;
                float cxa = (a==0) ? (s.mir[32]*s.Om[0] - s.mir[30]*s.Om[2])
                                   : (s.mir[30]*s.Om[1] - s.mir[31]*s.Om[0]);
                float vb = s.mir[21+a+1]*s.vi[0] + s.mir[24+a+1]*s.vi[1] + s.mir[27+a+1]*s.vi[2] + cxa;
                s.r2[a] = -vb;
            }
            __syncwarp();
            if (ln < 18) {
                int m = ln;
                float g0, g1;
                if (m == 0)      { float f = dt*GZ;  g0 = s.H[1]*f;  g1 = s.H[13]*f; }
                else if (m == 1) { float f = -dt*GZ; g0 = s.H[0]*f;  g1 = s.H[12]*f; }
                else if (m == 2) { g0 = 0.f; g1 = 0.f; }
                else if (m < 6)  { g0 = s.H[m-3]; g1 = s.H[12+m-3]; }
                else if (m < 9) {
                    int j = m - 6;
                    float l0 = -dt*skewrowdot(s.mir+9, s.mir, 0, j) - 0.5f*dt2*sgR(s.mir, 0, j);
                    float l1 = -dt*skewrowdot(s.mir+9, s.mir, 1, j) - 0.5f*dt2*sgR(s.mir, 1, j);
                    float l2 = -dt*skewrowdot(s.mir+9, s.mir, 2, j) - 0.5f*dt2*sgR(s.mir, 2, j);
                    g0 = s.H[3+j]  + s.H[0]*l0  + s.H[1]*l1  + s.H[2]*l2;
                    g1 = s.H[15+j] + s.H[12]*l0 + s.H[13]*l1 + s.H[14]*l2;
                } else if (m < 12) {
                    int j = m - 9;
                    float l0 = -dt*s.mir[j], l1 = -dt*s.mir[3+j], l2 = -dt*s.mir[6+j];
                    g0 = s.H[0]*l0  + s.H[1]*l1  + s.H[2]*l2;
                    g1 = s.H[12]*l0 + s.H[13]*l1 + s.H[14]*l2;
                } else { g0 = s.H[m-6]; g1 = s.H[12+m-6]; }
                s.G[m] = g0; s.G[18+m] = g1;
            }
            BAR_SYNC_128(1);
            // ---- c2: GA, HP, S ----
            {
                float acc = 0.f;
#pragma unroll
                for (int m = 0; m < 18; ++m) {
                    int col = (m < 6) ? m : m + 3;
                    acc += s.G[ga1A*18+m] * s.A[col*21 + ga1C];
                }
                s.GA[ln] = acc;
                if (ln < 10) {
                    int c2i = ln + 11;
                    float acc2 = 0.f;
#pragma unroll
                    for (int m = 0; m < 18; ++m) {
                        int col = (m < 6) ? m : m + 3;
                        acc2 += s.G[18+m] * s.A[col*21 + c2i];
                    }
                    s.GA[32+ln] = acc2;
                }
            }
            __syncwarp();
            {
                float hp = s.GA[ln];
                if (ga1C < 9) {
#pragma unroll
                    for (int m = 0; m < 12; ++m) {
                        int col = (m < 6) ? m : m + 3;
                        hp += s.GA[ga1A*21+col] * s.L[ga1C*12+m];
                    }
                }
                s.HP[ln] = hp;
                if (ln < 10) s.HP[32+ln] = s.GA[32+ln];
                if (ln >= 29) {
                    int m = ln - 29;
                    int a = (m == 2) ? 1 : 0;
                    int bb = (m == 0) ? 0 : 1;
                    float acc = 0.f;
#pragma unroll
                    for (int mm = 0; mm < 18; ++mm) {
                        int col = (mm < 6) ? mm : mm + 3;
                        acc += s.GA[a*21+col] * s.G[bb*18+mm];
                    }
                    if (a == bb) acc += s.in[cur][7+a];
                    s.S3[m] = acc;
                }
            }
            __syncwarp();
            __threadfence_block();
            BAR_ARRIVE_128(4);
            // ---- c4: dx + state update ----
            {
                const float S00 = s.S3[0], S01 = s.S3[1], S11 = s.S3[2];
                const float idet = 1.f / (S00*S11 - S01*S01);
                const float Si00 = S11*idet, Si01 = -S01*idet, Si11 = S00*idet;
                const float r0 = s.r2[0], r1 = s.r2[1];
                const float w0 = Si00*r0 + Si01*r1, w1 = Si01*r0 + Si11*r1;
#define DX(c) (s.HP[(c)]*w0 + s.HP[21+(c)]*w1)
                float sv = 0.f, tciu = 0.f;
                if (ln < 9) {
                    float xi[3] = {DX(0), DX(1), DX(2)};
                    float a2 = xi[0]*xi[0] + xi[1]*xi[1] + xi[2]*xi[2];
                    float c, sa, oc; so3c(a2, c, sa, oc);
                    float d0 = ((rp==0)?c:0.f) + oc*xi[rp]*xi[0] + sa*skf(xi, rp, 0);
                    float d1 = ((rp==1)?c:0.f) + oc*xi[rp]*xi[1] + sa*skf(xi, rp, 1);
                    float d2 = ((rp==2)?c:0.f) + oc*xi[rp]*xi[2] + sa*skf(xi, rp, 2);
                    sv = d0*s.Rotn[rq] + d1*s.Rotn[3+rq] + d2*s.Rotn[6+rq];
                } else if (ln < 15) {
                    float xi[3] = {DX(0), DX(1), DX(2)};
                    float a2 = xi[0]*xi[0] + xi[1]*xi[1] + xi[2]*xi[2];
                    float c, sa, oc; so3c(a2, c, sa, oc);
                    float j1 = j1c(a2);
                    float y0 = svW ? DX(6) : DX(3);
                    float y1 = svW ? DX(7) : DX(4);
                    float y2 = svW ? DX(8) : DX(5);
                    float J0 = ((svQ==0)?sa:0.f) + j1*xi[svQ]*xi[0] + oc*skf(xi, svQ, 0);
                    float J1 = ((svQ==1)?sa:0.f) + j1*xi[svQ]*xi[1] + oc*skf(xi, svQ, 1);
                    float J2 = ((svQ==2)?sa:0.f) + j1*xi[svQ]*xi[2] + oc*skf(xi, svQ, 2);
                    float x = J0*y0 + J1*y1 + J2*y2;
                    float d0 = ((svQ==0)?c:0.f) + oc*xi[svQ]*xi[0] + sa*skf(xi, svQ, 0);
                    float d1 = ((svQ==1)?c:0.f) + oc*xi[svQ]*xi[1] + sa*skf(xi, svQ, 1);
                    float d2 = ((svQ==2)?c:0.f) + oc*xi[svQ]*xi[2] + sa*skf(xi, svQ, 2);
                    const float* src = svW ? s.Pn3 : s.Vn;
                    sv = d0*src[0] + d1*src[1] + d2*src[2] + x;
                } else if (ln < 24) {
                    float yi[3] = {DX(15), DX(16), DX(17)};
                    float a2 = yi[0]*yi[0] + yi[1]*yi[1] + yi[2]*yi[2];
                    float c, sa, oc; so3c(a2, c, sa, oc);
                    float e0 = ((rcP==0)?c:0.f) + oc*yi[rcP]*yi[0] + sa*skf(yi, rcP, 0);
                    float e1 = ((rcP==1)?c:0.f) + oc*yi[rcP]*yi[1] + sa*skf(yi, rcP, 1);
                    float e2 = ((rcP==2)?c:0.f) + oc*yi[rcP]*yi[2] + sa*skf(yi, rcP, 2);
                    sv = e0*s.mir[21+rcQ] + e1*s.mir[24+rcQ] + e2*s.mir[27+rcQ];
                } else if (ln < 27) {
                    int q = ln - 24;
                    sv   = s.mir[15+q] + DX(9+q);
                    tciu = s.mir[30+q] + DX(18+q);
                } else if (ln < 30) {
                    int q = ln - 27;
                    sv = s.mir[18+q] + DX(12+q);
                }
#undef DX
                __syncwarp();
                if (ln < 15)       s.mir[ln] = sv;
                else if (ln < 24)  s.mir[21+(ln-15)] = sv;
                else if (ln < 27)  { s.mir[15+(ln-24)] = sv; s.mir[30+(ln-24)] = tciu; }
                else if (ln < 30)  s.mir[18+(ln-27)] = sv;
                if (ln < 9 && (i + 1 < N)) s.in[cur^1][ln] = pf;
                __syncwarp();
                if (i % 100 == 0) {
                    if (ln == 0) {
                        float X[9];
#pragma unroll
                        for (int m = 0; m < 9; ++m) X[m] = s.mir[m];
                        normrot(X);
#pragma unroll
                        for (int m = 0; m < 9; ++m) s.mir[m] = X[m];
                    }
                    if ((i % 1000 == 0) && ln == 1) {
                        float X[9];
#pragma unroll
                        for (int m = 0; m < 9; ++m) X[m] = s.mir[21+m];
                        normrot(X);
#pragma unroll
                        for (int m = 0; m < 9; ++m) s.mir[21+m] = X[m];
                    }
                }
                __syncwarp();
            }
            __threadfence_block();
            BAR_ARRIVE_128(5);
        }
    }

    // ---------- epilogue: final state row (W3) ----------
    if (!isMat) {
        *outP = s.mir[ln];
        if (ln == 0) *outP2 = s.mir[32];
    }
}

extern "C" void kernel_launch(void* const* d_in, const int* in_sizes, int n_in,
                              void* d_out, int out_size) {
    const float* t    = (const float*)d_in[0];
    const float* u    = (const float*)d_in[1];
    const float* mcov = (const float*)d_in[2];
    const float* vmes = (const float*)d_in[3];
    const float* ang0 = (const float*)d_in[5];
    float* out = (float*)d_out;
    int N = in_sizes[0];
    iekf_kernel<<<1, NT>>>(t, u, mcov, vmes, ang0, out, N);
}